// round 1
// baseline (speedup 1.0000x reference)
#include <cuda_runtime.h>
#include <math.h>

// Problem constants
#define BB 256
#define TT 30
#define ML 31
#define VV 10000
#define HH 512
#define EE 512
#define G4 2048            // 4*H
#define NROWS 7680         // TT*BB

// ---------------- device scratch (static; no allocations) ----------------
__device__ int   g_order[BB];
__device__ int   g_declen[BB];
__device__ int   g_cnt[TT];
__device__ float g_gp[BB * G4];                 // image proj + biases
__device__ float g_xp[NROWS * G4];              // embedding proj per (t,b)
__device__ float g_hbuf[2][BB * HH];            // double-buffered hidden
__device__ float g_cc[BB * HH];                 // cell state
__device__ float g_hall[NROWS * HH];            // h_new per active (t,b)
__device__ float g_gates[BB * G4];              // per-step gates scratch
__device__ float g_logits[(size_t)NROWS * VV];  // 307 MB logits scratch
__device__ float g_rowsum[NROWS];               // sum(exp(logits)) per row

// ---------------- prep: stable descending sort + targets ----------------
__global__ void k_prep(const int* __restrict__ w, const int* __restrict__ cap,
                       float* __restrict__ out, long long out_size) {
    __shared__ int lens[BB];
    int i = threadIdx.x;
    lens[i] = cap[i];
    __syncthreads();
    int li = lens[i];
    int rank = 0;
    #pragma unroll 8
    for (int j = 0; j < BB; j++) {
        int lj = lens[j];
        rank += (lj > li) || (lj == li && j < i);
    }
    g_order[rank]  = i;
    g_declen[rank] = li - 1;
    __syncthreads();   // makes g_order/g_declen visible within block

    if (i < TT) {
        int c = 0;
        for (int j = 0; j < BB; j++) c += (g_declen[j] > i);
        g_cnt[i] = c;
    }

    // outputs: target (B,30) then dec_len (B,), appended after preds, as float
    long long PRED = (long long)BB * ML * VV;
    if (out_size >= PRED + (long long)BB * TT + BB) {
        int src = g_order[i];
        for (int k = 0; k < TT; k++)
            out[PRED + (long long)i * TT + k] = (float)w[src * ML + k + 1];
        out[PRED + (long long)BB * TT + i] = (float)g_declen[i];
    }
}

__global__ void k_init() {
    int i = blockIdx.x * blockDim.x + threadIdx.x;
    if (i < BB * HH) {
        g_hbuf[0][i] = 0.f;
        g_hbuf[1][i] = 0.f;
        g_cc[i] = 0.f;
    }
    if (i < NROWS) g_rowsum[i] = 0.f;
}

// ---------------- tiled GEMM core (64x64 tile, K-chunk 16) ----------------
// A: 64 gathered rows (row ptrs in shared), row-major K-contig
// B: row-major [N][K] (all weight matrices are [out][in] K-contig)

#define GEMM_PROLOG() \
    __shared__ float As[16][65]; \
    __shared__ float Bs[16][65]; \
    __shared__ const float* ap[64]; \
    int tx = threadIdx.x, ty = threadIdx.y; \
    int tid = ty * 16 + tx; \
    int lm = tid >> 2; \
    int lk = (tid & 3) * 4; \
    float acc[4][4] = {{0.f,0.f,0.f,0.f},{0.f,0.f,0.f,0.f},{0.f,0.f,0.f,0.f},{0.f,0.f,0.f,0.f}};

#define GEMM_INNER() \
    _Pragma("unroll") \
    for (int kk = 0; kk < 16; kk++) { \
        float a0 = As[kk][ty], a1 = As[kk][ty+16], a2 = As[kk][ty+32], a3 = As[kk][ty+48]; \
        float b0 = Bs[kk][tx], b1 = Bs[kk][tx+16], b2 = Bs[kk][tx+32], b3 = Bs[kk][tx+48]; \
        acc[0][0] += a0*b0; acc[0][1] += a0*b1; acc[0][2] += a0*b2; acc[0][3] += a0*b3; \
        acc[1][0] += a1*b0; acc[1][1] += a1*b1; acc[1][2] += a1*b2; acc[1][3] += a1*b3; \
        acc[2][0] += a2*b0; acc[2][1] += a2*b1; acc[2][2] += a2*b2; acc[2][3] += a2*b3; \
        acc[3][0] += a3*b0; acc[3][1] += a3*b1; acc[3][2] += a3*b2; acc[3][3] += a3*b3; \
    }

// image projection: gp[b][j] = g_sorted[b] . W_ih[j][0:512] + b_ih[j] + b_hh[j]
__global__ __launch_bounds__(256) void k_gproj(
    const float* __restrict__ gimg, const float* __restrict__ Wih,
    const float* __restrict__ bih, const float* __restrict__ bhh) {
    GEMM_PROLOG();
    int m0 = blockIdx.y * 64;
    int n0 = blockIdx.x * 64;
    if (tid < 64) ap[tid] = gimg + (size_t)g_order[m0 + tid] * EE;
    __syncthreads();
    for (int k0 = 0; k0 < HH; k0 += 16) {
        float4 a = *(const float4*)(ap[lm] + k0 + lk);
        As[lk][lm] = a.x; As[lk+1][lm] = a.y; As[lk+2][lm] = a.z; As[lk+3][lm] = a.w;
        float4 b = *(const float4*)(Wih + (size_t)(n0 + lm) * 1024 + k0 + lk);
        Bs[lk][lm] = b.x; Bs[lk+1][lm] = b.y; Bs[lk+2][lm] = b.z; Bs[lk+3][lm] = b.w;
        __syncthreads();
        GEMM_INNER();
        __syncthreads();
    }
    #pragma unroll
    for (int i = 0; i < 4; i++) {
        int m = m0 + ty + 16 * i;
        #pragma unroll
        for (int j = 0; j < 4; j++) {
            int n = n0 + tx + 16 * j;
            g_gp[m * G4 + n] = acc[i][j] + bih[n] + bhh[n];
        }
    }
}

// embedding projection: xp[r][j] = emb[word(t,b)] . W_ih[j][512:1024]
__global__ __launch_bounds__(256) void k_xproj(
    const int* __restrict__ w, const float* __restrict__ emb,
    const float* __restrict__ Wih) {
    GEMM_PROLOG();
    int m0 = blockIdx.y * 64;          // global row r0
    int t = m0 / BB, b0 = m0 % BB;
    if (b0 >= g_cnt[t]) return;        // fully-inactive tile
    int n0 = blockIdx.x * 64;
    if (tid < 64) {
        int b = b0 + tid;
        int word = w[g_order[b] * ML + t];
        ap[tid] = emb + (size_t)word * EE;
    }
    __syncthreads();
    for (int k0 = 0; k0 < HH; k0 += 16) {
        float4 a = *(const float4*)(ap[lm] + k0 + lk);
        As[lk][lm] = a.x; As[lk+1][lm] = a.y; As[lk+2][lm] = a.z; As[lk+3][lm] = a.w;
        float4 b = *(const float4*)(Wih + (size_t)(n0 + lm) * 1024 + 512 + k0 + lk);
        Bs[lk][lm] = b.x; Bs[lk+1][lm] = b.y; Bs[lk+2][lm] = b.z; Bs[lk+3][lm] = b.w;
        __syncthreads();
        GEMM_INNER();
        __syncthreads();
    }
    #pragma unroll
    for (int i = 0; i < 4; i++) {
        int m = m0 + ty + 16 * i;
        #pragma unroll
        for (int j = 0; j < 4; j++)
            g_gates[0] += 0.f, g_xp[(size_t)m * G4 + n0 + tx + 16 * j] = acc[i][j];
    }
}

// recurrent gates GEMM: gates[b][j] = gp + xp[t] + h . W_hh[j]
__global__ __launch_bounds__(256) void k_gates(const float* __restrict__ Whh, int t) {
    GEMM_PROLOG();
    int m0 = blockIdx.y * 64;          // b
    if (m0 >= g_cnt[t]) return;
    int n0 = blockIdx.x * 64;
    const float* hrd = g_hbuf[t & 1];
    if (tid < 64) ap[tid] = hrd + (size_t)(m0 + tid) * HH;
    __syncthreads();
    for (int k0 = 0; k0 < HH; k0 += 16) {
        float4 a = *(const float4*)(ap[lm] + k0 + lk);
        As[lk][lm] = a.x; As[lk+1][lm] = a.y; As[lk+2][lm] = a.z; As[lk+3][lm] = a.w;
        float4 b = *(const float4*)(Whh + (size_t)(n0 + lm) * HH + k0 + lk);
        Bs[lk][lm] = b.x; Bs[lk+1][lm] = b.y; Bs[lk+2][lm] = b.z; Bs[lk+3][lm] = b.w;
        __syncthreads();
        GEMM_INNER();
        __syncthreads();
    }
    #pragma unroll
    for (int i = 0; i < 4; i++) {
        int m = m0 + ty + 16 * i;
        #pragma unroll
        for (int j = 0; j < 4; j++) {
            int n = n0 + tx + 16 * j;
            g_gates[m * G4 + n] = acc[i][j] + g_gp[m * G4 + n]
                                + g_xp[(size_t)(t * BB + m) * G4 + n];
        }
    }
}

// LSTM elementwise update
__global__ __launch_bounds__(256) void k_lstm(int t) {
    int idx = blockIdx.x * 256 + threadIdx.x;
    int b = idx >> 9;
    if (b >= g_cnt[t]) return;
    int n = idx & 511;
    float iv = g_gates[b * G4 + n];
    float fv = g_gates[b * G4 + 512 + n];
    float gv = g_gates[b * G4 + 1024 + n];
    float ov = g_gates[b * G4 + 1536 + n];
    iv = 1.f / (1.f + expf(-iv));
    fv = 1.f / (1.f + expf(-fv));
    ov = 1.f / (1.f + expf(-ov));
    gv = tanhf(gv);
    float cn = fv * g_cc[b * HH + n] + iv * gv;
    float hn = ov * tanhf(cn);
    g_cc[b * HH + n] = cn;
    g_hbuf[(t + 1) & 1][b * HH + n] = hn;
    g_hall[(size_t)(t * BB + b) * HH + n] = hn;
}

// vocab projection GEMM + exp-sum accumulation (no max needed: |logit| small)
__global__ __launch_bounds__(256) void k_out1(
    const float* __restrict__ Wout, const float* __restrict__ bout) {
    GEMM_PROLOG();
    int m0 = blockIdx.y * 64;
    int t = m0 / BB, b0 = m0 % BB;
    int cnt = g_cnt[t];
    if (b0 >= cnt) return;
    int n0 = blockIdx.x * 64;
    if (tid < 64) ap[tid] = g_hall + (size_t)(m0 + tid) * HH;
    __shared__ float red[64];
    if (tid < 64) red[tid] = 0.f;
    __syncthreads();
    for (int k0 = 0; k0 < HH; k0 += 16) {
        float4 a = *(const float4*)(ap[lm] + k0 + lk);
        As[lk][lm] = a.x; As[lk+1][lm] = a.y; As[lk+2][lm] = a.z; As[lk+3][lm] = a.w;
        float4 b = make_float4(0.f, 0.f, 0.f, 0.f);
        if (n0 + lm < VV)
            b = *(const float4*)(Wout + (size_t)(n0 + lm) * HH + k0 + lk);
        Bs[lk][lm] = b.x; Bs[lk+1][lm] = b.y; Bs[lk+2][lm] = b.z; Bs[lk+3][lm] = b.w;
        __syncthreads();
        GEMM_INNER();
        __syncthreads();
    }
    #pragma unroll
    for (int i = 0; i < 4; i++) {
        int mloc = ty + 16 * i;
        int m = m0 + mloc;
        bool act = (b0 + mloc) < cnt;
        float psum = 0.f;
        #pragma unroll
        for (int j = 0; j < 4; j++) {
            int n = n0 + tx + 16 * j;
            if (n < VV) {
                float v = acc[i][j] + bout[n];
                g_logits[(size_t)m * VV + n] = v;
                if (act) psum += expf(v);
            }
        }
        if (act) atomicAdd(&red[mloc], psum);
    }
    __syncthreads();
    if (tid < 64 && (b0 + tid) < cnt)
        atomicAdd(&g_rowsum[m0 + tid], red[tid]);
}

// final: preds[b][t][v] = logit - log(rowsum)  (inactive/pad already zeroed)
__global__ __launch_bounds__(256) void k_out2(float* __restrict__ out) {
    long long idx = (long long)blockIdx.x * 256 + threadIdx.x;
    const int perRow = VV / 4;             // 2500 float4 per row
    int r = (int)(idx / perRow);
    if (r >= NROWS) return;
    int v4 = (int)(idx % perRow);
    int t = r >> 8, b = r & 255;
    if (b >= g_cnt[t]) return;
    float ls = logf(g_rowsum[r]);
    float4 lv = *(const float4*)(g_logits + (size_t)r * VV + v4 * 4);
    float4 o;
    o.x = lv.x - ls; o.y = lv.y - ls; o.z = lv.z - ls; o.w = lv.w - ls;
    *(float4*)(out + (size_t)(b * ML + t) * VV + v4 * 4) = o;
}

// ---------------- launch ----------------
extern "C" void kernel_launch(void* const* d_in, const int* in_sizes, int n_in,
                              void* d_out, int out_size) {
    const float* gimg = (const float*)d_in[0];
    const int*   w    = (const int*)d_in[1];
    const int*   cap  = (const int*)d_in[2];
    const float* emb  = (const float*)d_in[3];
    const float* Wih  = (const float*)d_in[4];
    const float* Whh  = (const float*)d_in[5];
    const float* bih  = (const float*)d_in[6];
    const float* bhh  = (const float*)d_in[7];
    const float* Wout = (const float*)d_in[8];
    const float* bout = (const float*)d_in[9];
    float* out = (float*)d_out;

    size_t PRED = (size_t)BB * ML * VV;
    cudaMemsetAsync(d_out, 0, PRED * sizeof(float), 0);

    k_prep<<<1, 256>>>(w, cap, out, (long long)out_size);
    k_init<<<512, 256>>>();
    k_gproj<<<dim3(32, 4), dim3(16, 16)>>>(gimg, Wih, bih, bhh);
    k_xproj<<<dim3(32, 120), dim3(16, 16)>>>(w, emb, Wih);
    for (int t = 0; t < TT; t++) {
        k_gates<<<dim3(32, 4), dim3(16, 16)>>>(Whh, t);
        k_lstm<<<512, 256>>>(t);
    }
    k_out1<<<dim3(157, 120), dim3(16, 16)>>>(Wout, bout);
    k_out2<<<75000, 256>>>(out);
}

// round 2
// speedup vs baseline: 1.0769x; 1.0769x over previous
#include <cuda_runtime.h>
#include <mma.h>
#include <math.h>

using namespace nvcuda;

// Problem constants
#define BB 256
#define TT 30
#define ML 31
#define VV 10000
#define HH 512
#define G4 2048            // 4*H
#define NROWS 7680         // TT*BB
#define BK 32
#define LDA 36             // shared lda (32 + 4 pad)
#define LDC 132            // shared C ld (128 + 4 pad)
#define DSMEM_BYTES 67584  // 128*132*4 bytes (C) >= 2*128*36*4 (stage)

// ---------------- device scratch (static; no allocations) ----------------
__device__ int   g_order[BB];
__device__ int   g_declen[BB];
__device__ int   g_cnt[TT];
__device__ float g_gp[BB * G4];                  // image projection (no bias)
__device__ float g_xp[(size_t)NROWS * G4];       // embedding projection
__device__ float g_hbuf[2][BB * HH];             // double-buffered hidden
__device__ float g_cc[BB * HH];                  // cell state
__device__ float g_hall[(size_t)NROWS * HH];     // h_new per (t,b)
__device__ float g_rowsum[NROWS];                // sum(exp(logits)) per row

typedef wmma::fragment<wmma::matrix_a, 16, 16, 8, wmma::precision::tf32, wmma::row_major> FragA;
typedef wmma::fragment<wmma::matrix_b, 16, 16, 8, wmma::precision::tf32, wmma::col_major> FragB;
typedef wmma::fragment<wmma::accumulator, 16, 16, 8, float> FragC;

__device__ __forceinline__ void cvtA(FragA& f) {
    for (int q = 0; q < f.num_elements; q++) f.x[q] = wmma::__float_to_tf32(f.x[q]);
}
__device__ __forceinline__ void cvtB(FragB& f) {
    for (int q = 0; q < f.num_elements; q++) f.x[q] = wmma::__float_to_tf32(f.x[q]);
}

// ---------------- prep: stable descending sort + targets ----------------
__global__ void k_prep(const int* __restrict__ w, const int* __restrict__ cap,
                       float* __restrict__ out, long long out_size) {
    __shared__ int lens[BB];
    int i = threadIdx.x;
    lens[i] = cap[i];
    __syncthreads();
    int li = lens[i];
    int rank = 0;
    #pragma unroll 8
    for (int j = 0; j < BB; j++) {
        int lj = lens[j];
        rank += (lj > li) || (lj == li && j < i);
    }
    g_order[rank]  = i;
    g_declen[rank] = li - 1;
    __syncthreads();

    if (i < TT) {
        int c = 0;
        for (int j = 0; j < BB; j++) c += (g_declen[j] > i);
        g_cnt[i] = c;
    }

    long long PRED = (long long)BB * ML * VV;
    if (out_size >= PRED + (long long)BB * TT + BB) {
        int src = g_order[i];
        for (int k = 0; k < TT; k++)
            out[PRED + (long long)i * TT + k] = (float)w[src * ML + k + 1];
        out[PRED + (long long)BB * TT + i] = (float)g_declen[i];
    }
}

__global__ void k_init() {
    int i = blockIdx.x * blockDim.x + threadIdx.x;
    if (i < BB * HH) {
        g_hbuf[0][i] = 0.f;
        g_hbuf[1][i] = 0.f;
        g_cc[i] = 0.f;
    }
    if (i < NROWS) g_rowsum[i] = 0.f;
}

// ================= tf32 wmma GEMM kernels (128x128 tile, BK=32) =============
// 8 warps: warp = 4(m) x 2(n); warp tile 32x64 = 2x4 fragments.

#define WMMA_COMPUTE_CHUNK(As, Bs, cacc)                                          \
    __syncthreads();                                                              \
    _Pragma("unroll")                                                             \
    for (int kk = 0; kk < BK; kk += 8) {                                          \
        FragA a0, a1; FragB bf[4];                                                \
        wmma::load_matrix_sync(a0, &As[(wm * 32)      * LDA + kk], LDA);          \
        wmma::load_matrix_sync(a1, &As[(wm * 32 + 16) * LDA + kk], LDA);          \
        cvtA(a0); cvtA(a1);                                                       \
        _Pragma("unroll")                                                         \
        for (int j = 0; j < 4; j++) {                                             \
            wmma::load_matrix_sync(bf[j], &Bs[(wn * 64 + j * 16) * LDA + kk], LDA); \
            cvtB(bf[j]);                                                          \
        }                                                                         \
        _Pragma("unroll")                                                         \
        for (int j = 0; j < 4; j++) {                                             \
            wmma::mma_sync(cacc[0][j], a0, bf[j], cacc[0][j]);                    \
            wmma::mma_sync(cacc[1][j], a1, bf[j], cacc[1][j]);                    \
        }                                                                         \
    }                                                                             \
    __syncthreads();

// ---- image projection: gp[b][n] = gimg[order[b]] . W_ih[n][0:512] ----
__global__ __launch_bounds__(256) void k_gproj(const float* __restrict__ gimg,
                                               const float* __restrict__ Wih) {
    __shared__ float As[128 * LDA];
    __shared__ float Bs[128 * LDA];
    __shared__ const float* ap[128];
    int tid = threadIdx.x;
    int m0 = blockIdx.y * 128, n0 = blockIdx.x * 128;
    if (tid < 128) ap[tid] = gimg + (size_t)g_order[m0 + tid] * HH;
    int warp = tid >> 5, wm = warp & 3, wn = warp >> 2;
    FragC c[2][4];
    #pragma unroll
    for (int i = 0; i < 2; i++)
        #pragma unroll
        for (int j = 0; j < 4; j++) wmma::fill_fragment(c[i][j], 0.f);
    int srow = tid >> 1, scol = (tid & 1) * 16;
    __syncthreads();
    for (int k0 = 0; k0 < HH; k0 += BK) {
        const float* arp = ap[srow] + k0 + scol;
        const float* brp = Wih + (size_t)(n0 + srow) * 1024 + k0 + scol;
        #pragma unroll
        for (int q = 0; q < 4; q++) {
            *(float4*)&As[srow * LDA + scol + q * 4] = *(const float4*)(arp + q * 4);
            *(float4*)&Bs[srow * LDA + scol + q * 4] = *(const float4*)(brp + q * 4);
        }
        WMMA_COMPUTE_CHUNK(As, Bs, c);
    }
    #pragma unroll
    for (int i = 0; i < 2; i++)
        #pragma unroll
        for (int j = 0; j < 4; j++)
            wmma::store_matrix_sync(g_gp + (size_t)(m0 + wm * 32 + i * 16) * G4
                                         + n0 + wn * 64 + j * 16,
                                    c[i][j], G4, wmma::mem_row_major);
}

// ---- embedding projection: xp[t*B+b][n] = emb[word(t,b)] . W_ih[n][512:1024] ----
__global__ __launch_bounds__(256) void k_xproj(const int* __restrict__ w,
                                               const float* __restrict__ emb,
                                               const float* __restrict__ Wih) {
    __shared__ float As[128 * LDA];
    __shared__ float Bs[128 * LDA];
    __shared__ const float* ap[128];
    int tid = threadIdx.x;
    int m0 = blockIdx.y * 128;
    int t = m0 >> 8, b0 = m0 & 255;
    if (b0 >= g_cnt[t]) return;
    int n0 = blockIdx.x * 128;
    if (tid < 128) {
        int word = w[g_order[b0 + tid] * ML + t];
        ap[tid] = emb + (size_t)word * HH;
    }
    int warp = tid >> 5, wm = warp & 3, wn = warp >> 2;
    FragC c[2][4];
    #pragma unroll
    for (int i = 0; i < 2; i++)
        #pragma unroll
        for (int j = 0; j < 4; j++) wmma::fill_fragment(c[i][j], 0.f);
    int srow = tid >> 1, scol = (tid & 1) * 16;
    __syncthreads();
    for (int k0 = 0; k0 < HH; k0 += BK) {
        const float* arp = ap[srow] + k0 + scol;
        const float* brp = Wih + (size_t)(n0 + srow) * 1024 + 512 + k0 + scol;
        #pragma unroll
        for (int q = 0; q < 4; q++) {
            *(float4*)&As[srow * LDA + scol + q * 4] = *(const float4*)(arp + q * 4);
            *(float4*)&Bs[srow * LDA + scol + q * 4] = *(const float4*)(brp + q * 4);
        }
        WMMA_COMPUTE_CHUNK(As, Bs, c);
    }
    #pragma unroll
    for (int i = 0; i < 2; i++)
        #pragma unroll
        for (int j = 0; j < 4; j++)
            wmma::store_matrix_sync(g_xp + (size_t)(m0 + wm * 32 + i * 16) * G4
                                         + n0 + wn * 64 + j * 16,
                                    c[i][j], G4, wmma::mem_row_major);
}

// ---- fused recurrent step: gates GEMM (h @ W_hh^T) + LSTM elementwise ----
// Block: 128 b x (4 gates x 32 h). blockIdx.x = h-tile (h0 = x*32), .y = b-tile.
__global__ __launch_bounds__(256) void k_step(const float* __restrict__ Whh,
                                              const float* __restrict__ bih,
                                              const float* __restrict__ bhh, int t) {
    extern __shared__ float dsm[];
    float* As = dsm;
    float* Bs = dsm + 128 * LDA;
    float* Cs = dsm;                       // reused after compute
    int tid = threadIdx.x;
    int cnt = g_cnt[t];
    int b0 = blockIdx.y * 128;
    if (b0 >= cnt) return;
    int h0 = blockIdx.x * 32;
    const float* hrd = g_hbuf[t & 1];
    int warp = tid >> 5, wm = warp & 3, wn = warp >> 2;
    FragC c[2][4];
    #pragma unroll
    for (int i = 0; i < 2; i++)
        #pragma unroll
        for (int j = 0; j < 4; j++) wmma::fill_fragment(c[i][j], 0.f);
    int srow = tid >> 1, scol = (tid & 1) * 16;
    int gate = srow >> 5, hh_s = srow & 31;
    const float* brow = Whh + (size_t)(gate * 512 + h0 + hh_s) * HH;
    const float* arow = hrd + (size_t)(b0 + srow) * HH;
    for (int k0 = 0; k0 < HH; k0 += BK) {
        #pragma unroll
        for (int q = 0; q < 4; q++) {
            *(float4*)&As[srow * LDA + scol + q * 4] = *(const float4*)(arow + k0 + scol + q * 4);
            *(float4*)&Bs[srow * LDA + scol + q * 4] = *(const float4*)(brow + k0 + scol + q * 4);
        }
        WMMA_COMPUTE_CHUNK(As, Bs, c);
    }
    #pragma unroll
    for (int i = 0; i < 2; i++)
        #pragma unroll
        for (int j = 0; j < 4; j++)
            wmma::store_matrix_sync(&Cs[(wm * 32 + i * 16) * LDC + wn * 64 + j * 16],
                                    c[i][j], LDC, wmma::mem_row_major);
    __syncthreads();

    // LSTM elementwise over 128b x 32h pairs
    #pragma unroll
    for (int it = 0; it < 16; it++) {
        int p = it * 256 + tid;            // 0..4095
        int row = p >> 5;                  // local b
        int hh = p & 31;
        int b = b0 + row;
        if (b >= cnt) continue;
        size_t xpb = (size_t)(t * BB + b) * G4;
        int n_i = 0 * 512 + h0 + hh;
        int n_f = 1 * 512 + h0 + hh;
        int n_g = 2 * 512 + h0 + hh;
        int n_o = 3 * 512 + h0 + hh;
        float iv = Cs[row * LDC + 0  + hh] + g_gp[b * G4 + n_i] + g_xp[xpb + n_i] + bih[n_i] + bhh[n_i];
        float fv = Cs[row * LDC + 32 + hh] + g_gp[b * G4 + n_f] + g_xp[xpb + n_f] + bih[n_f] + bhh[n_f];
        float gv = Cs[row * LDC + 64 + hh] + g_gp[b * G4 + n_g] + g_xp[xpb + n_g] + bih[n_g] + bhh[n_g];
        float ov = Cs[row * LDC + 96 + hh] + g_gp[b * G4 + n_o] + g_xp[xpb + n_o] + bih[n_o] + bhh[n_o];
        iv = 1.f / (1.f + __expf(-iv));
        fv = 1.f / (1.f + __expf(-fv));
        ov = 1.f / (1.f + __expf(-ov));
        gv = tanhf(gv);
        int hidx = b * HH + h0 + hh;
        float cn = fv * g_cc[hidx] + iv * gv;
        float hn = ov * tanhf(cn);
        g_cc[hidx] = cn;
        g_hbuf[(t + 1) & 1][hidx] = hn;
        g_hall[(size_t)(t * BB + b) * HH + h0 + hh] = hn;
    }
}

// ---- vocab projection: logits -> out (in place) + rowsum of exp ----
__global__ __launch_bounds__(256) void k_out1(const float* __restrict__ Wout,
                                              const float* __restrict__ bout,
                                              float* __restrict__ out) {
    extern __shared__ float dsm[];
    float* As = dsm;
    float* Bs = dsm + 128 * LDA;
    float* Cs = dsm;
    int tid = threadIdx.x;
    int m0 = blockIdx.y * 128;
    int t = m0 >> 8, b0 = m0 & 255;
    int cnt = g_cnt[t];
    if (b0 >= cnt) return;
    int n0 = blockIdx.x * 128;
    int warp = tid >> 5, wm = warp & 3, wn = warp >> 2;
    FragC c[2][4];
    #pragma unroll
    for (int i = 0; i < 2; i++)
        #pragma unroll
        for (int j = 0; j < 4; j++) wmma::fill_fragment(c[i][j], 0.f);
    int srow = tid >> 1, scol = (tid & 1) * 16;
    const float* arow = g_hall + (size_t)(m0 + srow) * HH;
    int nb = n0 + srow;
    const float* brow = Wout + (size_t)nb * HH;
    bool bvalid = (nb < VV);
    for (int k0 = 0; k0 < HH; k0 += BK) {
        #pragma unroll
        for (int q = 0; q < 4; q++) {
            *(float4*)&As[srow * LDA + scol + q * 4] = *(const float4*)(arow + k0 + scol + q * 4);
            float4 bv = make_float4(0.f, 0.f, 0.f, 0.f);
            if (bvalid) bv = *(const float4*)(brow + k0 + scol + q * 4);
            *(float4*)&Bs[srow * LDA + scol + q * 4] = bv;
        }
        WMMA_COMPUTE_CHUNK(As, Bs, c);
    }
    #pragma unroll
    for (int i = 0; i < 2; i++)
        #pragma unroll
        for (int j = 0; j < 4; j++)
            wmma::store_matrix_sync(&Cs[(wm * 32 + i * 16) * LDC + wn * 64 + j * 16],
                                    c[i][j], LDC, wmma::mem_row_major);
    __syncthreads();

    // epilogue: bias + exp-sum + in-place logit write (float4)
    int row = tid >> 1;
    int cb = (tid & 1) * 64;
    int b = b0 + row;
    if (b < cnt) {
        size_t obase = ((size_t)b * ML + t) * VV;
        float psum = 0.f;
        #pragma unroll
        for (int q = 0; q < 16; q++) {
            int n = n0 + cb + q * 4;
            if (n < VV) {
                float4 cv = *(const float4*)&Cs[row * LDC + cb + q * 4];
                float4 bo = *(const float4*)(bout + n);
                float4 v;
                v.x = cv.x + bo.x; v.y = cv.y + bo.y;
                v.z = cv.z + bo.z; v.w = cv.w + bo.w;
                *(float4*)(out + obase + n) = v;
                psum += __expf(v.x) + __expf(v.y) + __expf(v.z) + __expf(v.w);
            }
        }
        atomicAdd(&g_rowsum[m0 + row], psum);
    }
}

// ---- final: in-place log-softmax correction ----
__global__ __launch_bounds__(256) void k_out2(float* __restrict__ out) {
    long long idx = (long long)blockIdx.x * 256 + threadIdx.x;
    const int perRow = VV / 4;             // 2500 float4 per row
    int r = (int)(idx / perRow);
    if (r >= NROWS) return;
    int v4 = (int)(idx % perRow);
    int t = r >> 8, b = r & 255;
    if (b >= g_cnt[t]) return;
    float ls = logf(g_rowsum[r]);
    size_t p = ((size_t)b * ML + t) * VV + v4 * 4;
    float4 lv = *(const float4*)(out + p);
    float4 o;
    o.x = lv.x - ls; o.y = lv.y - ls; o.z = lv.z - ls; o.w = lv.w - ls;
    *(float4*)(out + p) = o;
}

// ---------------- launch ----------------
extern "C" void kernel_launch(void* const* d_in, const int* in_sizes, int n_in,
                              void* d_out, int out_size) {
    const float* gimg = (const float*)d_in[0];
    const int*   w    = (const int*)d_in[1];
    const int*   cap  = (const int*)d_in[2];
    const float* emb  = (const float*)d_in[3];
    const float* Wih  = (const float*)d_in[4];
    const float* Whh  = (const float*)d_in[5];
    const float* bih  = (const float*)d_in[6];
    const float* bhh  = (const float*)d_in[7];
    const float* Wout = (const float*)d_in[8];
    const float* bout = (const float*)d_in[9];
    float* out = (float*)d_out;

    cudaFuncSetAttribute(k_step, cudaFuncAttributeMaxDynamicSharedMemorySize, DSMEM_BYTES);
    cudaFuncSetAttribute(k_out1, cudaFuncAttributeMaxDynamicSharedMemorySize, DSMEM_BYTES);

    size_t PRED = (size_t)BB * ML * VV;
    cudaMemsetAsync(d_out, 0, PRED * sizeof(float), 0);

    k_prep<<<1, 256>>>(w, cap, out, (long long)out_size);
    k_init<<<512, 256>>>();
    k_gproj<<<dim3(16, 2), 256>>>(gimg, Wih);
    k_xproj<<<dim3(16, 60), 256>>>(w, emb, Wih);
    for (int t = 0; t < TT; t++)
        k_step<<<dim3(16, 2), 256, DSMEM_BYTES>>>(Whh, bih, bhh, t);
    k_out1<<<dim3(79, 60), 256, DSMEM_BYTES>>>(Wout, bout, out);
    k_out2<<<75000, 256>>>(out);
}